// round 13
// baseline (speedup 1.0000x reference)
#include <cuda_runtime.h>
#include <cuda_bf16.h>
#include <cstdint>
#include <math.h>

#define N_OSC 32
#define CONVC 1000.0f

// -------- scratch (no allocations allowed) --------
__device__ __align__(16) float g_h1[4096];
__device__ __align__(16) float g_h2[4096];
__device__ __align__(16) float g_params[2112];
__device__ __align__(16) float g_cpg[64];
__device__ __align__(16) float g_h3[2048];
__device__ __align__(16) float g_h4[2048];

// ============ block-per-row matvec with PDL weight prefetch ============
// Rows < resRows load weights with default .ca (stay L2-resident across graph
// replays); rows >= resRows use __ldcs (evict-first streaming) so they never
// evict the resident set. L2 ~126 MB; resident budget ~111 MB.
template <bool RELU, int C4>
__global__ __launch_bounds__(256) void matvec_b(const float* __restrict__ W,
                                                const float* __restrict__ b,
                                                const float* __restrict__ x,
                                                float* __restrict__ y,
                                                int resRows) {
    int row = blockIdx.x;
    const float4* __restrict__ w4 = reinterpret_cast<const float4*>(W) + (size_t)row * C4;
    const float4* __restrict__ x4 = reinterpret_cast<const float4*>(x);

    float4 wreg[C4 / 256];
    if (row < resRows) {
        #pragma unroll
        for (int k = 0; k < C4 / 256; ++k)
            wreg[k] = w4[threadIdx.x + k * 256];
    } else {
        #pragma unroll
        for (int k = 0; k < C4 / 256; ++k)
            wreg[k] = __ldcs(&w4[threadIdx.x + k * 256]);
    }
    float bias = (threadIdx.x == 0) ? b[row] : 0.f;

    cudaGridDependencySynchronize();   // wait for predecessor's x

    float s = 0.f;
    #pragma unroll
    for (int k = 0; k < C4 / 256; ++k) {
        float4 v = x4[threadIdx.x + k * 256];
        s += wreg[k].x * v.x + wreg[k].y * v.y + wreg[k].z * v.z + wreg[k].w * v.w;
    }

    #pragma unroll
    for (int o = 16; o; o >>= 1) s += __shfl_xor_sync(0xFFFFFFFFu, s, o);
    __shared__ float red[8];
    if ((threadIdx.x & 31) == 0) red[threadIdx.x >> 5] = s;
    __syncthreads();
    if (threadIdx.x < 8) {
        float v = red[threadIdx.x];
        #pragma unroll
        for (int o = 4; o; o >>= 1) v += __shfl_xor_sync(0xFFu, v, o);
        if (threadIdx.x == 0) {
            v += bias;
            if (RELU) v = fmaxf(v, 0.f);
            y[row] = v;
        }
    }
}

// ============ layer 1: cols = 2049 (2048 from x + timestep) ============
// iW0 kept L2-resident (default loads).
__global__ __launch_bounds__(256) void matvec_l1(const float* __restrict__ W,
                                                 const float* __restrict__ b,
                                                 const float* __restrict__ x,
                                                 const float* __restrict__ ts,
                                                 float* __restrict__ y) {
    int row = blockIdx.x;
    const float* __restrict__ w = W + (size_t)row * 2049;

    float s = 0.f;
    #pragma unroll
    for (int k = 0; k < 8; ++k) {
        int c = threadIdx.x + k * 256;
        s += w[c] * x[c];
    }
    if (threadIdx.x == 0) s += w[2048] * ts[0];

    #pragma unroll
    for (int o = 16; o; o >>= 1) s += __shfl_xor_sync(0xFFFFFFFFu, s, o);
    __shared__ float red[8];
    if ((threadIdx.x & 31) == 0) red[threadIdx.x >> 5] = s;
    __syncthreads();
    if (threadIdx.x < 8) {
        float v = red[threadIdx.x];
        #pragma unroll
        for (int o = 4; o; o >>= 1) v += __shfl_xor_sync(0xFFu, v, o);
        if (threadIdx.x == 0) {
            v += b[row];
            y[row] = fmaxf(v, 0.f);
        }
    }
}

// ============ small layer [2048 x 64]: warp-per-row, PDL prefetch ============
__global__ void matvec_small64(const float* __restrict__ W,
                               const float* __restrict__ b,
                               const float* __restrict__ x,
                               float* __restrict__ y, int rows) {
    int warp = (blockIdx.x * blockDim.x + threadIdx.x) >> 5;
    int lane = threadIdx.x & 31;

    float4 w = make_float4(0.f, 0.f, 0.f, 0.f);
    float bias = 0.f;
    if (warp < rows) {
        if (lane < 16)
            w = reinterpret_cast<const float4*>(W + (size_t)warp * 64)[lane];
        if (lane == 0) bias = b[warp];
    }

    cudaGridDependencySynchronize();   // wait for cpg

    if (warp >= rows) return;
    float s = 0.f;
    if (lane < 16) {
        float4 v = reinterpret_cast<const float4*>(x)[lane];
        s = w.x * v.x + w.y * v.y + w.z * v.z + w.w * v.w;
    }
    #pragma unroll
    for (int o = 8; o; o >>= 1) s += __shfl_xor_sync(0xFFFFFFFFu, s, o);
    if (lane == 0) y[warp] = fmaxf(s + bias, 0.f);
}

// ============ CPG ODE, RK4 3/8 rule — single warp, registers + __sinf ============
// Lane i <-> oscillator i. Coupling row cw[i][:], pb[i][:] in registers.
// Only phases cross lanes, via s_ph[] (same-address LDS = broadcast).
// Replicates reference slicing exactly: phase_dots go into the a_dot slot,
// and post-step "ph" is read from that slot for cpg_out.
__global__ __launch_bounds__(32) void cpg_ode_kernel(
        const float* __restrict__ state,
        const float* __restrict__ ts,
        float* __restrict__ d_out_state /* 96 floats */) {
    __shared__ float s_ph[N_OSC];

    int i = threadIdx.x;   // lane = oscillator

    // independent inputs: prefetch before dependency sync
    float h   = ts[0];
    float ya  = state[i];
    float yad = state[N_OSC + i];
    float yph = state[2 * N_OSC + i];

    cudaGridDependencySynchronize();   // wait for g_params (layer-3 output)

    float cw[N_OSC], pb[N_OSC];
    {
        const float4* cw4 = reinterpret_cast<const float4*>(g_params + 2 * N_OSC) + i * 8;
        const float4* pb4 = reinterpret_cast<const float4*>(g_params + 2 * N_OSC + N_OSC * N_OSC) + i * 8;
        #pragma unroll
        for (int k = 0; k < 8; ++k) {
            float4 c = cw4[k];
            cw[4 * k + 0] = c.x; cw[4 * k + 1] = c.y; cw[4 * k + 2] = c.z; cw[4 * k + 3] = c.w;
            float4 p = pb4[k];
            pb[4 * k + 0] = p.x; pb[4 * k + 1] = p.y; pb[4 * k + 2] = p.z; pb[4 * k + 3] = p.w;
        }
    }
    float ia  = g_params[i];
    float ifr = g_params[N_OSC + i];

    float k1a, k1ad, k1ph, k2a, k2ad, k2ph, k3a, k3ad, k3ph, k4a, k4ad, k4ph;

    auto stage = [&](float ea, float ead, float eph,
                     float& ka, float& kad, float& kph) {
        s_ph[i] = eph;
        __syncwarp();
        float t = 0.f;
        #pragma unroll
        for (int j = 0; j < N_OSC; ++j)
            t += cw[j] * __sinf(s_ph[j] - eph - pb[j]);
        __syncwarp();
        kad = ifr + ea * t;                                // phase_dots
        ka  = ead;                                         // a_dot
        kph = CONVC * (CONVC * 0.25f * (ia - ea) - ead);   // a_dd
    };

    stage(ya, yad, yph, k1a, k1ad, k1ph);
    stage(ya + h * k1a / 3.0f, yad + h * k1ad / 3.0f, yph + h * k1ph / 3.0f,
          k2a, k2ad, k2ph);
    stage(ya + h * (k2a - k1a / 3.0f),
          yad + h * (k2ad - k1ad / 3.0f),
          yph + h * (k2ph - k1ph / 3.0f),
          k3a, k3ad, k3ph);
    stage(ya + h * (k1a - k2a + k3a),
          yad + h * (k1ad - k2ad + k3ad),
          yph + h * (k1ph - k2ph + k3ph),
          k4a, k4ad, k4ph);

    float yna  = ya  + h * 0.125f * (k1a  + 3.0f * (k2a  + k3a)  + k4a);
    float ynad = yad + h * 0.125f * (k1ad + 3.0f * (k2ad + k3ad) + k4ad);
    float ynph = yph + h * 0.125f * (k1ph + 3.0f * (k2ph + k3ph) + k4ph);

    d_out_state[i]             = yna;
    d_out_state[N_OSC + i]     = ynad;
    d_out_state[2 * N_OSC + i] = ynph;

    // reference reads ns[:n] as a and ns[n:2n] (the a_dot slot) as ph
    g_cpg[i]         = yna * __cosf(ynad);
    g_cpg[N_OSC + i] = yna * __sinf(ynad);
}

// -------- launch helper with PDL attribute --------
template <typename K, typename... Args>
static void launch_pdl(K kernel, dim3 grid, dim3 block, Args... args) {
    cudaLaunchConfig_t cfg = {};
    cfg.gridDim = grid;
    cfg.blockDim = block;
    cudaLaunchAttribute attr[1];
    attr[0].id = cudaLaunchAttributeProgrammaticStreamSerialization;
    attr[0].val.programmaticStreamSerializationAllowed = 1;
    cfg.attrs = attr;
    cfg.numAttrs = 1;
    cudaLaunchKernelEx(&cfg, kernel, args...);
}

extern "C" void kernel_launch(void* const* d_in, const int* in_sizes, int n_in,
                              void* d_out, int out_size) {
    const float* state = (const float*)d_in[0];
    const float* x     = (const float*)d_in[1];
    const float* ts    = (const float*)d_in[2];
    const float* iW0   = (const float*)d_in[3];
    const float* ib0   = (const float*)d_in[4];
    const float* iW1   = (const float*)d_in[5];
    const float* ib1   = (const float*)d_in[6];
    const float* iW2   = (const float*)d_in[7];
    const float* ib2   = (const float*)d_in[8];
    const float* oW0   = (const float*)d_in[9];
    const float* ob0   = (const float*)d_in[10];
    const float* oW1   = (const float*)d_in[11];
    const float* ob1   = (const float*)d_in[12];
    const float* oW2   = (const float*)d_in[13];
    const float* ob2   = (const float*)d_in[14];
    float* out = (float*)d_out;   // [new_state(96), out(1024)]

    float* h1;  cudaGetSymbolAddress((void**)&h1,  g_h1);
    float* h2;  cudaGetSymbolAddress((void**)&h2,  g_h2);
    float* pr;  cudaGetSymbolAddress((void**)&pr,  g_params);
    float* cpg; cudaGetSymbolAddress((void**)&cpg, g_cpg);
    float* h3;  cudaGetSymbolAddress((void**)&h3,  g_h3);
    float* h4;  cudaGetSymbolAddress((void**)&h4,  g_h4);

    // L2-residency plan (L2 ~126 MB):
    //   resident (.ca): iW0 33.6 + iW2 34.6 + oW1 16.8 + oW2 8.4 + oW0 0.5
    //                 + iW1 rows [0,1024) 16.8  =  ~110.7 MB
    //   streamed (__ldcs): iW1 rows [1024,4096)  =  50.3 MB
    const int IW1_RES_ROWS = 1024;

    // 1) h1 = relu(iW0 @ [x, ts] + ib0)   [4096 x 2049]
    matvec_l1<<<4096, 256>>>(iW0, ib0, x, ts, h1);

    // 2) h2 = relu(iW1 @ h1 + ib1)        [4096 x 4096]  (partially streamed)
    launch_pdl(matvec_b<true, 1024>, dim3(4096), dim3(256), iW1, ib1, h1, h2, IW1_RES_ROWS);

    // 3) params = iW2 @ h2 + ib2          [2112 x 4096]
    launch_pdl(matvec_b<false, 1024>, dim3(2112), dim3(256), iW2, ib2, h2, pr, 2112);

    // 4) RK4 step + cpg_out; writes new_state to d_out[0:96]
    launch_pdl(cpg_ode_kernel, dim3(1), dim3(32), state, ts, out);

    // 5) h3 = relu(oW0 @ cpg + ob0)       [2048 x 64]
    launch_pdl(matvec_small64, dim3((2048 * 32) / 256), dim3(256), oW0, ob0, cpg, h3, 2048);

    // 6) h4 = relu(oW1 @ h3 + ob1)        [2048 x 2048]
    launch_pdl(matvec_b<true, 512>, dim3(2048), dim3(256), oW1, ob1, h3, h4, 2048);

    // 7) out = oW2 @ h4 + ob2             [1024 x 2048] -> d_out[96:1120]
    launch_pdl(matvec_b<false, 512>, dim3(1024), dim3(256), oW2, ob2, h4, out + 96, 1024);
}

// round 14
// speedup vs baseline: 1.1142x; 1.1142x over previous
#include <cuda_runtime.h>
#include <cuda_bf16.h>
#include <cstdint>
#include <math.h>

#define N_OSC 32
#define CONVC 1000.0f

// -------- scratch (no allocations allowed) --------
__device__ __align__(16) float g_h1[4096];
__device__ __align__(16) float g_h2[4096];
__device__ __align__(16) float g_params[2112];
__device__ __align__(16) float g_cpg[64];
__device__ __align__(16) float g_h3[2048];
__device__ __align__(16) float g_h4[2048];

// ============ block-per-row matvec with PDL weight prefetch ============
// STREAM=true -> weights loaded with __ldcs (evict-first): keeps the big
// single-use matrix from evicting the L2-resident weight set between
// graph replays. STREAM=false -> default .ca load (persist in L2).
// Measured: resident set ~94 MB works; ~111 MB thrashes (R13). Keep iW1
// fully streamed.
template <bool RELU, int C4, bool STREAM>
__global__ __launch_bounds__(256) void matvec_b(const float* __restrict__ W,
                                                const float* __restrict__ b,
                                                const float* __restrict__ x,
                                                float* __restrict__ y) {
    int row = blockIdx.x;
    const float4* __restrict__ w4 = reinterpret_cast<const float4*>(W) + (size_t)row * C4;
    const float4* __restrict__ x4 = reinterpret_cast<const float4*>(x);

    float4 wreg[C4 / 256];
    #pragma unroll
    for (int k = 0; k < C4 / 256; ++k)
        wreg[k] = STREAM ? __ldcs(&w4[threadIdx.x + k * 256])
                         : w4[threadIdx.x + k * 256];
    float bias = (threadIdx.x == 0) ? b[row] : 0.f;

    cudaGridDependencySynchronize();   // wait for predecessor's x

    float s = 0.f;
    #pragma unroll
    for (int k = 0; k < C4 / 256; ++k) {
        float4 v = x4[threadIdx.x + k * 256];
        s += wreg[k].x * v.x + wreg[k].y * v.y + wreg[k].z * v.z + wreg[k].w * v.w;
    }

    #pragma unroll
    for (int o = 16; o; o >>= 1) s += __shfl_xor_sync(0xFFFFFFFFu, s, o);
    __shared__ float red[8];
    if ((threadIdx.x & 31) == 0) red[threadIdx.x >> 5] = s;
    __syncthreads();
    if (threadIdx.x < 8) {
        float v = red[threadIdx.x];
        #pragma unroll
        for (int o = 4; o; o >>= 1) v += __shfl_xor_sync(0xFFu, v, o);
        if (threadIdx.x == 0) {
            v += bias;
            if (RELU) v = fmaxf(v, 0.f);
            y[row] = v;
        }
    }
}

// ============ layer 1: cols = 2049 (2048 from x + timestep) ============
// iW0 kept L2-resident (default loads).
__global__ __launch_bounds__(256) void matvec_l1(const float* __restrict__ W,
                                                 const float* __restrict__ b,
                                                 const float* __restrict__ x,
                                                 const float* __restrict__ ts,
                                                 float* __restrict__ y) {
    int row = blockIdx.x;
    const float* __restrict__ w = W + (size_t)row * 2049;

    float s = 0.f;
    #pragma unroll
    for (int k = 0; k < 8; ++k) {
        int c = threadIdx.x + k * 256;
        s += w[c] * x[c];
    }
    if (threadIdx.x == 0) s += w[2048] * ts[0];

    #pragma unroll
    for (int o = 16; o; o >>= 1) s += __shfl_xor_sync(0xFFFFFFFFu, s, o);
    __shared__ float red[8];
    if ((threadIdx.x & 31) == 0) red[threadIdx.x >> 5] = s;
    __syncthreads();
    if (threadIdx.x < 8) {
        float v = red[threadIdx.x];
        #pragma unroll
        for (int o = 4; o; o >>= 1) v += __shfl_xor_sync(0xFFu, v, o);
        if (threadIdx.x == 0) {
            v += b[row];
            y[row] = fmaxf(v, 0.f);
        }
    }
}

// ============ small layer [2048 x 64]: warp-per-row, PDL prefetch ============
__global__ void matvec_small64(const float* __restrict__ W,
                               const float* __restrict__ b,
                               const float* __restrict__ x,
                               float* __restrict__ y, int rows) {
    int warp = (blockIdx.x * blockDim.x + threadIdx.x) >> 5;
    int lane = threadIdx.x & 31;

    float4 w = make_float4(0.f, 0.f, 0.f, 0.f);
    float bias = 0.f;
    if (warp < rows) {
        if (lane < 16)
            w = reinterpret_cast<const float4*>(W + (size_t)warp * 64)[lane];
        if (lane == 0) bias = b[warp];
    }

    cudaGridDependencySynchronize();   // wait for cpg

    if (warp >= rows) return;
    float s = 0.f;
    if (lane < 16) {
        float4 v = reinterpret_cast<const float4*>(x)[lane];
        s = w.x * v.x + w.y * v.y + w.z * v.z + w.w * v.w;
    }
    #pragma unroll
    for (int o = 8; o; o >>= 1) s += __shfl_xor_sync(0xFFFFFFFFu, s, o);
    if (lane == 0) y[warp] = fmaxf(s + bias, 0.f);
}

// ============ CPG ODE, RK4 3/8 rule — single warp, registers + __sinf ============
// Lane i <-> oscillator i. Coupling row cw[i][:], pb[i][:] in registers.
// Only phases cross lanes, via s_ph[] (same-address LDS = broadcast).
// Replicates reference slicing exactly: phase_dots go into the a_dot slot,
// and post-step "ph" is read from that slot for cpg_out.
__global__ __launch_bounds__(32) void cpg_ode_kernel(
        const float* __restrict__ state,
        const float* __restrict__ ts,
        float* __restrict__ d_out_state /* 96 floats */) {
    __shared__ float s_ph[N_OSC];

    int i = threadIdx.x;   // lane = oscillator

    // independent inputs: prefetch before dependency sync
    float h   = ts[0];
    float ya  = state[i];
    float yad = state[N_OSC + i];
    float yph = state[2 * N_OSC + i];

    cudaGridDependencySynchronize();   // wait for g_params (layer-3 output)

    float cw[N_OSC], pb[N_OSC];
    {
        const float4* cw4 = reinterpret_cast<const float4*>(g_params + 2 * N_OSC) + i * 8;
        const float4* pb4 = reinterpret_cast<const float4*>(g_params + 2 * N_OSC + N_OSC * N_OSC) + i * 8;
        #pragma unroll
        for (int k = 0; k < 8; ++k) {
            float4 c = cw4[k];
            cw[4 * k + 0] = c.x; cw[4 * k + 1] = c.y; cw[4 * k + 2] = c.z; cw[4 * k + 3] = c.w;
            float4 p = pb4[k];
            pb[4 * k + 0] = p.x; pb[4 * k + 1] = p.y; pb[4 * k + 2] = p.z; pb[4 * k + 3] = p.w;
        }
    }
    float ia  = g_params[i];
    float ifr = g_params[N_OSC + i];

    float k1a, k1ad, k1ph, k2a, k2ad, k2ph, k3a, k3ad, k3ph, k4a, k4ad, k4ph;

    auto stage = [&](float ea, float ead, float eph,
                     float& ka, float& kad, float& kph) {
        s_ph[i] = eph;
        __syncwarp();
        float t = 0.f;
        #pragma unroll
        for (int j = 0; j < N_OSC; ++j)
            t += cw[j] * __sinf(s_ph[j] - eph - pb[j]);
        __syncwarp();
        kad = ifr + ea * t;                                // phase_dots
        ka  = ead;                                         // a_dot
        kph = CONVC * (CONVC * 0.25f * (ia - ea) - ead);   // a_dd
    };

    stage(ya, yad, yph, k1a, k1ad, k1ph);
    stage(ya + h * k1a / 3.0f, yad + h * k1ad / 3.0f, yph + h * k1ph / 3.0f,
          k2a, k2ad, k2ph);
    stage(ya + h * (k2a - k1a / 3.0f),
          yad + h * (k2ad - k1ad / 3.0f),
          yph + h * (k2ph - k1ph / 3.0f),
          k3a, k3ad, k3ph);
    stage(ya + h * (k1a - k2a + k3a),
          yad + h * (k1ad - k2ad + k3ad),
          yph + h * (k1ph - k2ph + k3ph),
          k4a, k4ad, k4ph);

    float yna  = ya  + h * 0.125f * (k1a  + 3.0f * (k2a  + k3a)  + k4a);
    float ynad = yad + h * 0.125f * (k1ad + 3.0f * (k2ad + k3ad) + k4ad);
    float ynph = yph + h * 0.125f * (k1ph + 3.0f * (k2ph + k3ph) + k4ph);

    d_out_state[i]             = yna;
    d_out_state[N_OSC + i]     = ynad;
    d_out_state[2 * N_OSC + i] = ynph;

    // reference reads ns[:n] as a and ns[n:2n] (the a_dot slot) as ph
    g_cpg[i]         = yna * __cosf(ynad);
    g_cpg[N_OSC + i] = yna * __sinf(ynad);
}

// -------- launch helper with PDL attribute --------
template <typename K, typename... Args>
static void launch_pdl(K kernel, dim3 grid, dim3 block, Args... args) {
    cudaLaunchConfig_t cfg = {};
    cfg.gridDim = grid;
    cfg.blockDim = block;
    cudaLaunchAttribute attr[1];
    attr[0].id = cudaLaunchAttributeProgrammaticStreamSerialization;
    attr[0].val.programmaticStreamSerializationAllowed = 1;
    cfg.attrs = attr;
    cfg.numAttrs = 1;
    cudaLaunchKernelEx(&cfg, kernel, args...);
}

extern "C" void kernel_launch(void* const* d_in, const int* in_sizes, int n_in,
                              void* d_out, int out_size) {
    const float* state = (const float*)d_in[0];
    const float* x     = (const float*)d_in[1];
    const float* ts    = (const float*)d_in[2];
    const float* iW0   = (const float*)d_in[3];
    const float* ib0   = (const float*)d_in[4];
    const float* iW1   = (const float*)d_in[5];
    const float* ib1   = (const float*)d_in[6];
    const float* iW2   = (const float*)d_in[7];
    const float* ib2   = (const float*)d_in[8];
    const float* oW0   = (const float*)d_in[9];
    const float* ob0   = (const float*)d_in[10];
    const float* oW1   = (const float*)d_in[11];
    const float* ob1   = (const float*)d_in[12];
    const float* oW2   = (const float*)d_in[13];
    const float* ob2   = (const float*)d_in[14];
    float* out = (float*)d_out;   // [new_state(96), out(1024)]

    float* h1;  cudaGetSymbolAddress((void**)&h1,  g_h1);
    float* h2;  cudaGetSymbolAddress((void**)&h2,  g_h2);
    float* pr;  cudaGetSymbolAddress((void**)&pr,  g_params);
    float* cpg; cudaGetSymbolAddress((void**)&cpg, g_cpg);
    float* h3;  cudaGetSymbolAddress((void**)&h3,  g_h3);
    float* h4;  cudaGetSymbolAddress((void**)&h4,  g_h4);

    // L2-residency plan (measured optimum, R12):
    //   resident (.ca): iW0 33.6 + iW2 34.6 + oW1 16.8 + oW2 8.4 + oW0 0.5
    //                 = ~94 MB  (L2 ~126 MB nominal; ~111 MB thrashes)
    //   streamed (__ldcs): iW1 (67 MB), single-use per replay

    // 1) h1 = relu(iW0 @ [x, ts] + ib0)   [4096 x 2049]
    matvec_l1<<<4096, 256>>>(iW0, ib0, x, ts, h1);

    // 2) h2 = relu(iW1 @ h1 + ib1)        [4096 x 4096]  (STREAMED)
    launch_pdl(matvec_b<true, 1024, true>, dim3(4096), dim3(256), iW1, ib1, h1, h2);

    // 3) params = iW2 @ h2 + ib2          [2112 x 4096]
    launch_pdl(matvec_b<false, 1024, false>, dim3(2112), dim3(256), iW2, ib2, h2, pr);

    // 4) RK4 step + cpg_out; writes new_state to d_out[0:96]
    launch_pdl(cpg_ode_kernel, dim3(1), dim3(32), state, ts, out);

    // 5) h3 = relu(oW0 @ cpg + ob0)       [2048 x 64]
    launch_pdl(matvec_small64, dim3((2048 * 32) / 256), dim3(256), oW0, ob0, cpg, h3, 2048);

    // 6) h4 = relu(oW1 @ h3 + ob1)        [2048 x 2048]
    launch_pdl(matvec_b<true, 512, false>, dim3(2048), dim3(256), oW1, ob1, h3, h4);

    // 7) out = oW2 @ h4 + ob2             [1024 x 2048] -> d_out[96:1120]
    launch_pdl(matvec_b<false, 512, false>, dim3(1024), dim3(256), oW2, ob2, h4, out + 96);
}

// round 15
// speedup vs baseline: 1.1243x; 1.0091x over previous
#include <cuda_runtime.h>
#include <cuda_bf16.h>
#include <cstdint>
#include <math.h>

#define N_OSC 32
#define CONVC 1000.0f

// -------- scratch (no allocations allowed) --------
__device__ __align__(16) float g_h1[4096];
__device__ __align__(16) float g_h2[4096];
__device__ __align__(16) float g_params[2112];
__device__ __align__(16) float g_cpg[64];
__device__ __align__(16) float g_h3[2048];
__device__ __align__(16) float g_h4[2048];

// ============ block-per-row matvec with PDL weight prefetch ============
// STREAM=true -> weights loaded with __ldcs (evict-first): keeps the big
// single-use matrix from evicting the L2-resident weight set between
// graph replays. STREAM=false -> default .ca load (persist in L2).
// Measured: resident set ~94 MB works; ~111 MB thrashes (R13).
// cudaTriggerProgrammaticLaunchCompletion() fires right after the weight
// prefetch issues, so the NEXT kernel's prefetch overlaps this kernel's
// last-wave compute (GridDependencySynchronize still enforces data deps).
template <bool RELU, int C4, bool STREAM>
__global__ __launch_bounds__(256) void matvec_b(const float* __restrict__ W,
                                                const float* __restrict__ b,
                                                const float* __restrict__ x,
                                                float* __restrict__ y) {
    int row = blockIdx.x;
    const float4* __restrict__ w4 = reinterpret_cast<const float4*>(W) + (size_t)row * C4;
    const float4* __restrict__ x4 = reinterpret_cast<const float4*>(x);

    float4 wreg[C4 / 256];
    #pragma unroll
    for (int k = 0; k < C4 / 256; ++k)
        wreg[k] = STREAM ? __ldcs(&w4[threadIdx.x + k * 256])
                         : w4[threadIdx.x + k * 256];
    float bias = (threadIdx.x == 0) ? b[row] : 0.f;

    cudaTriggerProgrammaticLaunchCompletion();   // let successor start ASAP

    cudaGridDependencySynchronize();   // wait for predecessor's x

    float s = 0.f;
    #pragma unroll
    for (int k = 0; k < C4 / 256; ++k) {
        float4 v = x4[threadIdx.x + k * 256];
        s += wreg[k].x * v.x + wreg[k].y * v.y + wreg[k].z * v.z + wreg[k].w * v.w;
    }

    #pragma unroll
    for (int o = 16; o; o >>= 1) s += __shfl_xor_sync(0xFFFFFFFFu, s, o);
    __shared__ float red[8];
    if ((threadIdx.x & 31) == 0) red[threadIdx.x >> 5] = s;
    __syncthreads();
    if (threadIdx.x < 8) {
        float v = red[threadIdx.x];
        #pragma unroll
        for (int o = 4; o; o >>= 1) v += __shfl_xor_sync(0xFFu, v, o);
        if (threadIdx.x == 0) {
            v += bias;
            if (RELU) v = fmaxf(v, 0.f);
            y[row] = v;
        }
    }
}

// ============ layer 1: cols = 2049 (2048 from x + timestep) ============
// iW0 kept L2-resident (default loads). Trigger early: successor (layer 2,
// the DRAM-streamed big layer) starts its weight stream while this
// LTS-bound layer computes.
__global__ __launch_bounds__(256) void matvec_l1(const float* __restrict__ W,
                                                 const float* __restrict__ b,
                                                 const float* __restrict__ x,
                                                 const float* __restrict__ ts,
                                                 float* __restrict__ y) {
    cudaTriggerProgrammaticLaunchCompletion();

    int row = blockIdx.x;
    const float* __restrict__ w = W + (size_t)row * 2049;

    float s = 0.f;
    #pragma unroll
    for (int k = 0; k < 8; ++k) {
        int c = threadIdx.x + k * 256;
        s += w[c] * x[c];
    }
    if (threadIdx.x == 0) s += w[2048] * ts[0];

    #pragma unroll
    for (int o = 16; o; o >>= 1) s += __shfl_xor_sync(0xFFFFFFFFu, s, o);
    __shared__ float red[8];
    if ((threadIdx.x & 31) == 0) red[threadIdx.x >> 5] = s;
    __syncthreads();
    if (threadIdx.x < 8) {
        float v = red[threadIdx.x];
        #pragma unroll
        for (int o = 4; o; o >>= 1) v += __shfl_xor_sync(0xFFu, v, o);
        if (threadIdx.x == 0) {
            v += b[row];
            y[row] = fmaxf(v, 0.f);
        }
    }
}

// ============ small layer [2048 x 64]: warp-per-row, PDL prefetch ============
__global__ void matvec_small64(const float* __restrict__ W,
                               const float* __restrict__ b,
                               const float* __restrict__ x,
                               float* __restrict__ y, int rows) {
    int warp = (blockIdx.x * blockDim.x + threadIdx.x) >> 5;
    int lane = threadIdx.x & 31;

    float4 w = make_float4(0.f, 0.f, 0.f, 0.f);
    float bias = 0.f;
    if (warp < rows) {
        if (lane < 16)
            w = reinterpret_cast<const float4*>(W + (size_t)warp * 64)[lane];
        if (lane == 0) bias = b[warp];
    }

    cudaTriggerProgrammaticLaunchCompletion();

    cudaGridDependencySynchronize();   // wait for cpg

    if (warp >= rows) return;
    float s = 0.f;
    if (lane < 16) {
        float4 v = reinterpret_cast<const float4*>(x)[lane];
        s = w.x * v.x + w.y * v.y + w.z * v.z + w.w * v.w;
    }
    #pragma unroll
    for (int o = 8; o; o >>= 1) s += __shfl_xor_sync(0xFFFFFFFFu, s, o);
    if (lane == 0) y[warp] = fmaxf(s + bias, 0.f);
}

// ============ CPG ODE, RK4 3/8 rule — single warp, registers + __sinf ============
// Lane i <-> oscillator i. Coupling row cw[i][:], pb[i][:] in registers.
// Only phases cross lanes, via s_ph[] (same-address LDS = broadcast).
// Replicates reference slicing exactly: phase_dots go into the a_dot slot,
// and post-step "ph" is read from that slot for cpg_out.
__global__ __launch_bounds__(32) void cpg_ode_kernel(
        const float* __restrict__ state,
        const float* __restrict__ ts,
        float* __restrict__ d_out_state /* 96 floats */) {
    __shared__ float s_ph[N_OSC];

    int i = threadIdx.x;   // lane = oscillator

    // independent inputs: prefetch before dependency sync
    float h   = ts[0];
    float ya  = state[i];
    float yad = state[N_OSC + i];
    float yph = state[2 * N_OSC + i];

    cudaTriggerProgrammaticLaunchCompletion();   // single block: fires at once

    cudaGridDependencySynchronize();   // wait for g_params (layer-3 output)

    float cw[N_OSC], pb[N_OSC];
    {
        const float4* cw4 = reinterpret_cast<const float4*>(g_params + 2 * N_OSC) + i * 8;
        const float4* pb4 = reinterpret_cast<const float4*>(g_params + 2 * N_OSC + N_OSC * N_OSC) + i * 8;
        #pragma unroll
        for (int k = 0; k < 8; ++k) {
            float4 c = cw4[k];
            cw[4 * k + 0] = c.x; cw[4 * k + 1] = c.y; cw[4 * k + 2] = c.z; cw[4 * k + 3] = c.w;
            float4 p = pb4[k];
            pb[4 * k + 0] = p.x; pb[4 * k + 1] = p.y; pb[4 * k + 2] = p.z; pb[4 * k + 3] = p.w;
        }
    }
    float ia  = g_params[i];
    float ifr = g_params[N_OSC + i];

    float k1a, k1ad, k1ph, k2a, k2ad, k2ph, k3a, k3ad, k3ph, k4a, k4ad, k4ph;

    auto stage = [&](float ea, float ead, float eph,
                     float& ka, float& kad, float& kph) {
        s_ph[i] = eph;
        __syncwarp();
        float t = 0.f;
        #pragma unroll
        for (int j = 0; j < N_OSC; ++j)
            t += cw[j] * __sinf(s_ph[j] - eph - pb[j]);
        __syncwarp();
        kad = ifr + ea * t;                                // phase_dots
        ka  = ead;                                         // a_dot
        kph = CONVC * (CONVC * 0.25f * (ia - ea) - ead);   // a_dd
    };

    stage(ya, yad, yph, k1a, k1ad, k1ph);
    stage(ya + h * k1a / 3.0f, yad + h * k1ad / 3.0f, yph + h * k1ph / 3.0f,
          k2a, k2ad, k2ph);
    stage(ya + h * (k2a - k1a / 3.0f),
          yad + h * (k2ad - k1ad / 3.0f),
          yph + h * (k2ph - k1ph / 3.0f),
          k3a, k3ad, k3ph);
    stage(ya + h * (k1a - k2a + k3a),
          yad + h * (k1ad - k2ad + k3ad),
          yph + h * (k1ph - k2ph + k3ph),
          k4a, k4ad, k4ph);

    float yna  = ya  + h * 0.125f * (k1a  + 3.0f * (k2a  + k3a)  + k4a);
    float ynad = yad + h * 0.125f * (k1ad + 3.0f * (k2ad + k3ad) + k4ad);
    float ynph = yph + h * 0.125f * (k1ph + 3.0f * (k2ph + k3ph) + k4ph);

    d_out_state[i]             = yna;
    d_out_state[N_OSC + i]     = ynad;
    d_out_state[2 * N_OSC + i] = ynph;

    // reference reads ns[:n] as a and ns[n:2n] (the a_dot slot) as ph
    g_cpg[i]         = yna * __cosf(ynad);
    g_cpg[N_OSC + i] = yna * __sinf(ynad);
}

// -------- launch helper with PDL attribute --------
template <typename K, typename... Args>
static void launch_pdl(K kernel, dim3 grid, dim3 block, Args... args) {
    cudaLaunchConfig_t cfg = {};
    cfg.gridDim = grid;
    cfg.blockDim = block;
    cudaLaunchAttribute attr[1];
    attr[0].id = cudaLaunchAttributeProgrammaticStreamSerialization;
    attr[0].val.programmaticStreamSerializationAllowed = 1;
    cfg.attrs = attr;
    cfg.numAttrs = 1;
    cudaLaunchKernelEx(&cfg, kernel, args...);
}

extern "C" void kernel_launch(void* const* d_in, const int* in_sizes, int n_in,
                              void* d_out, int out_size) {
    const float* state = (const float*)d_in[0];
    const float* x     = (const float*)d_in[1];
    const float* ts    = (const float*)d_in[2];
    const float* iW0   = (const float*)d_in[3];
    const float* ib0   = (const float*)d_in[4];
    const float* iW1   = (const float*)d_in[5];
    const float* ib1   = (const float*)d_in[6];
    const float* iW2   = (const float*)d_in[7];
    const float* ib2   = (const float*)d_in[8];
    const float* oW0   = (const float*)d_in[9];
    const float* ob0   = (const float*)d_in[10];
    const float* oW1   = (const float*)d_in[11];
    const float* ob1   = (const float*)d_in[12];
    const float* oW2   = (const float*)d_in[13];
    const float* ob2   = (const float*)d_in[14];
    float* out = (float*)d_out;   // [new_state(96), out(1024)]

    float* h1;  cudaGetSymbolAddress((void**)&h1,  g_h1);
    float* h2;  cudaGetSymbolAddress((void**)&h2,  g_h2);
    float* pr;  cudaGetSymbolAddress((void**)&pr,  g_params);
    float* cpg; cudaGetSymbolAddress((void**)&cpg, g_cpg);
    float* h3;  cudaGetSymbolAddress((void**)&h3,  g_h3);
    float* h4;  cudaGetSymbolAddress((void**)&h4,  g_h4);

    // L2-residency plan (measured optimum, R12):
    //   resident (.ca): iW0 33.6 + iW2 34.6 + oW1 16.8 + oW2 8.4 + oW0 0.5
    //                 = ~94 MB  (L2 ~126 MB nominal; ~111 MB thrashes)
    //   streamed (__ldcs): iW1 (67 MB), single-use per replay

    // 1) h1 = relu(iW0 @ [x, ts] + ib0)   [4096 x 2049]
    launch_pdl(matvec_l1, dim3(4096), dim3(256), iW0, ib0, x, ts, h1);

    // 2) h2 = relu(iW1 @ h1 + ib1)        [4096 x 4096]  (STREAMED)
    launch_pdl(matvec_b<true, 1024, true>, dim3(4096), dim3(256), iW1, ib1, h1, h2);

    // 3) params = iW2 @ h2 + ib2          [2112 x 4096]
    launch_pdl(matvec_b<false, 1024, false>, dim3(2112), dim3(256), iW2, ib2, h2, pr);

    // 4) RK4 step + cpg_out; writes new_state to d_out[0:96]
    launch_pdl(cpg_ode_kernel, dim3(1), dim3(32), state, ts, out);

    // 5) h3 = relu(oW0 @ cpg + ob0)       [2048 x 64]
    launch_pdl(matvec_small64, dim3((2048 * 32) / 256), dim3(256), oW0, ob0, cpg, h3, 2048);

    // 6) h4 = relu(oW1 @ h3 + ob1)        [2048 x 2048]
    launch_pdl(matvec_b<true, 512, false>, dim3(2048), dim3(256), oW1, ob1, h3, h4);

    // 7) out = oW2 @ h4 + ob2             [1024 x 2048] -> d_out[96:1120]
    launch_pdl(matvec_b<false, 512, false>, dim3(1024), dim3(256), oW2, ob2, h4, out + 96);
}